// round 6
// baseline (speedup 1.0000x reference)
#include <cuda_runtime.h>
#include <math.h>

#define BB 8
#define NN 1024
#define MM 1024
#define D  512
#define HH 8
#define DS 64
#define ROWS (BB*NN)          // 8192
#define NEGV (-1e38f)
#define SCALE 0.04419417382415922f   // 1/sqrt(512)

typedef unsigned long long ull;

// packed f32x2 helpers (sm_100+)
__device__ __forceinline__ ull pk2(float lo, float hi) {
    ull r;
    asm("mov.b64 %0, {%1, %2};" : "=l"(r) : "f"(lo), "f"(hi));
    return r;
}
__device__ __forceinline__ float2 upk2(ull v) {
    float2 f;
    asm("mov.b64 {%0, %1}, %2;" : "=f"(f.x), "=f"(f.y) : "l"(v));
    return f;
}
#define FMA2(d, a, b) asm("fma.rn.f32x2 %0, %1, %2, %0;" : "+l"(d) : "l"(a), "l"(b))
#define MUL2(d, a)    asm("mul.rn.f32x2 %0, %0, %1;"    : "+l"(d) : "l"(a))

// Scratch (device globals; no allocation allowed)
__device__ float S_q  [ROWS*D];
__device__ float S_k  [ROWS*D];
__device__ float S_v  [ROWS*D];
__device__ float S_att[ROWS*D];
__device__ float S_t1 [ROWS*D];
__device__ float S_t2 [ROWS*D];

// ---------------------------------------------------------------------------
// SGEMM: C[ROWS,512] = A[ROWS,512] @ B[512,512]
// FLAGS: bit0 = +bias, bit1 = relu, bit2 = zero A rows where amask[row]!=0
// 128x64 tile, k-chunk 16, 256 threads, 4x8 microtile, FFMA2 inner,
// double-buffered smem, 3 CTAs/SM.
// ---------------------------------------------------------------------------
template<int FLAGS>
__global__ void __launch_bounds__(256, 3) sgemm_k(
    const float* __restrict__ A, const float* __restrict__ Bmat,
    const float* __restrict__ bias, const int* __restrict__ amask,
    float* __restrict__ C)
{
    __shared__ float As[2][16][132];   // [k][row] transposed
    __shared__ float Bs[2][16][68];    // [k][col]
    const int t  = threadIdx.x;
    const int tx = t & 7, ty = t >> 3;            // tx: 8 col-groups, ty: 32 row-groups
    const int row0 = blockIdx.y * 128, col0 = blockIdx.x * 64;
    const int ar = t >> 1, ak = (t & 1) * 8;      // A: 2 threads/row, 8 k each
    const int bk = t >> 4, bn = (t & 15) * 4;     // B: 16 k-rows, 16 threads/row

    const bool am = (FLAGS & 4) && (amask[row0 + ar] != 0);
    const float* Aptr = A + (size_t)(row0 + ar) * D + ak;
    const float* Bptr = Bmat + (size_t)bk * D + col0 + bn;

    float4 av0 = *(const float4*)Aptr;
    float4 av1 = *(const float4*)(Aptr + 4);
    float4 bv  = *(const float4*)Bptr;
    if (am) { av0 = make_float4(0,0,0,0); av1 = make_float4(0,0,0,0); }
    As[0][ak+0][ar] = av0.x; As[0][ak+1][ar] = av0.y;
    As[0][ak+2][ar] = av0.z; As[0][ak+3][ar] = av0.w;
    As[0][ak+4][ar] = av1.x; As[0][ak+5][ar] = av1.y;
    As[0][ak+6][ar] = av1.z; As[0][ak+7][ar] = av1.w;
    *(float4*)&Bs[0][bk][bn] = bv;
    __syncthreads();

    ull acc2[4][4] = {};   // 4 rows x (2 cols-pairs per 32-block x 2 blocks)

    #pragma unroll 1
    for (int c = 0; c < 32; c++) {
        int cur = c & 1;
        if (c < 31) {
            av0 = *(const float4*)(Aptr + (c + 1) * 16);
            av1 = *(const float4*)(Aptr + (c + 1) * 16 + 4);
            bv  = *(const float4*)(Bptr + (size_t)(c + 1) * 16 * D);
            if (am) { av0 = make_float4(0,0,0,0); av1 = make_float4(0,0,0,0); }
        }
        #pragma unroll
        for (int kk = 0; kk < 16; kk++) {
            float4 a  = *(const float4*)&As[cur][kk][ty * 4];
            float4 b0 = *(const float4*)&Bs[cur][kk][tx * 4];
            float4 b1 = *(const float4*)&Bs[cur][kk][32 + tx * 4];
            ull bp0 = pk2(b0.x, b0.y), bp1 = pk2(b0.z, b0.w);
            ull bp2 = pk2(b1.x, b1.y), bp3 = pk2(b1.z, b1.w);
            float ra[4] = {a.x, a.y, a.z, a.w};
            #pragma unroll
            for (int i = 0; i < 4; i++) {
                ull ap = pk2(ra[i], ra[i]);
                FMA2(acc2[i][0], ap, bp0);
                FMA2(acc2[i][1], ap, bp1);
                FMA2(acc2[i][2], ap, bp2);
                FMA2(acc2[i][3], ap, bp3);
            }
        }
        if (c < 31) {
            int nxt = cur ^ 1;
            As[nxt][ak+0][ar] = av0.x; As[nxt][ak+1][ar] = av0.y;
            As[nxt][ak+2][ar] = av0.z; As[nxt][ak+3][ar] = av0.w;
            As[nxt][ak+4][ar] = av1.x; As[nxt][ak+5][ar] = av1.y;
            As[nxt][ak+6][ar] = av1.z; As[nxt][ak+7][ar] = av1.w;
            *(float4*)&Bs[nxt][bk][bn] = bv;
            __syncthreads();
        }
    }

    #pragma unroll
    for (int i = 0; i < 4; i++) {
        int row = row0 + ty * 4 + i;
        #pragma unroll
        for (int cb = 0; cb < 2; cb++) {
            int col = col0 + cb * 32 + tx * 4;
            float2 v0 = upk2(acc2[i][cb * 2 + 0]);
            float2 v1 = upk2(acc2[i][cb * 2 + 1]);
            float vv[4] = {v0.x, v0.y, v1.x, v1.y};
            #pragma unroll
            for (int j = 0; j < 4; j++) {
                if (FLAGS & 1) vv[j] += bias[col + j];
                if (FLAGS & 2) vv[j] = fmaxf(vv[j], 0.f);
            }
            *(float4*)&C[(size_t)row * D + col] =
                make_float4(vv[0], vv[1], vv[2], vv[3]);
        }
    }
}

// ---------------------------------------------------------------------------
// Flash attention: one CTA = (b,h, 64-query tile). Online softmax over M=1024.
// 16x16 threads, 4q x 4k per thread, FFMA2, register softmax, 3 CTAs/SM.
// ---------------------------------------------------------------------------
__global__ void __launch_bounds__(256, 3) attn_k(
    const float* __restrict__ q, const float* __restrict__ k,
    const float* __restrict__ v,
    const int* __restrict__ xmask,
    const int* __restrict__ ymask,
    float* __restrict__ att)
{
    extern __shared__ float sm[];
    float* Qs = sm;              // [d=64][q=68]  pre-scaled
    float* Ks = Qs + 64 * 68;    // [d=64][k=68]
    float* Vs = Ks + 64 * 68;    // [m=64][d=68]
    float* Ss = Vs + 64 * 68;    // [k=64][q=68]  (exp'd P)

    const int bh = blockIdx.y;
    const int b  = bh >> 3, h = bh & 7;
    const int n0 = blockIdx.x * 64;
    const int t  = threadIdx.x;
    const int tx = t & 15, ty = t >> 4;

    const float* qbase = q + ((size_t)b * NN + n0) * D + h * DS;
    const float* kbase = k + (size_t)b * MM * D + h * DS;
    const float* vbase = v + (size_t)b * MM * D + h * DS;
    const int* ymb = ymask + b * MM;
    const int* xmb = xmask + b * NN;

    // Load Q tile (64x64) transposed into [d][q], scaled
    {
        int r = t >> 2;
        #pragma unroll
        for (int dd = 0; dd < 4; dd++) {
            int d4 = (t & 3) * 4 + dd * 16;
            float4 qa = *(const float4*)&qbase[(size_t)r * D + d4];
            Qs[(d4+0)*68 + r] = qa.x * SCALE; Qs[(d4+1)*68 + r] = qa.y * SCALE;
            Qs[(d4+2)*68 + r] = qa.z * SCALE; Qs[(d4+3)*68 + r] = qa.w * SCALE;
        }
    }

    float mi[4] = {-3.0e38f, -3.0e38f, -3.0e38f, -3.0e38f};
    float li[4] = {0.f, 0.f, 0.f, 0.f};
    ull acc2[4][2] = {};

    for (int m0 = 0; m0 < MM; m0 += 64) {
        __syncthreads();
        {
            int r = t >> 2;
            #pragma unroll
            for (int dd = 0; dd < 4; dd++) {
                int d4 = (t & 3) * 4 + dd * 16;
                float4 kv = *(const float4*)&kbase[(size_t)(m0 + r) * D + d4];
                Ks[(d4+0)*68 + r] = kv.x; Ks[(d4+1)*68 + r] = kv.y;
                Ks[(d4+2)*68 + r] = kv.z; Ks[(d4+3)*68 + r] = kv.w;
                float4 vv = *(const float4*)&vbase[(size_t)(m0 + r) * D + d4];
                *(float4*)&Vs[r * 68 + d4] = vv;
            }
        }
        __syncthreads();

        // S = (Q*SCALE).K^T : 4q x 4k per thread, FFMA2
        ull s2[4][2] = {};
        #pragma unroll 8
        for (int d = 0; d < 64; d++) {
            float4 qa = *(const float4*)&Qs[d * 68 + ty * 4];
            float4 kq = *(const float4*)&Ks[d * 68 + tx * 4];
            ull kp0 = pk2(kq.x, kq.y), kp1 = pk2(kq.z, kq.w);
            float qq[4] = {qa.x, qa.y, qa.z, qa.w};
            #pragma unroll
            for (int i = 0; i < 4; i++) {
                ull ap = pk2(qq[i], qq[i]);
                FMA2(s2[i][0], ap, kp0);
                FMA2(s2[i][1], ap, kp1);
            }
        }

        // unpack + key-mask
        float s[4][4];
        int km0 = ymb[m0 + tx * 4 + 0], km1 = ymb[m0 + tx * 4 + 1];
        int km2 = ymb[m0 + tx * 4 + 2], km3 = ymb[m0 + tx * 4 + 3];
        #pragma unroll
        for (int i = 0; i < 4; i++) {
            float2 v0 = upk2(s2[i][0]);
            float2 v1 = upk2(s2[i][1]);
            s[i][0] = km0 ? NEGV : v0.x;
            s[i][1] = km1 ? NEGV : v0.y;
            s[i][2] = km2 ? NEGV : v1.x;
            s[i][3] = km3 ? NEGV : v1.y;
        }

        // online softmax in registers (reduce across 16 tx lanes)
        #pragma unroll
        for (int i = 0; i < 4; i++) {
            float mx = fmaxf(fmaxf(s[i][0], s[i][1]), fmaxf(s[i][2], s[i][3]));
            mx = fmaxf(mx, __shfl_xor_sync(0xffffffffu, mx, 1));
            mx = fmaxf(mx, __shfl_xor_sync(0xffffffffu, mx, 2));
            mx = fmaxf(mx, __shfl_xor_sync(0xffffffffu, mx, 4));
            mx = fmaxf(mx, __shfl_xor_sync(0xffffffffu, mx, 8));
            float mnew = fmaxf(mi[i], mx);
            float corr = __expf(mi[i] - mnew);
            float p0 = __expf(s[i][0] - mnew);
            float p1 = __expf(s[i][1] - mnew);
            float p2 = __expf(s[i][2] - mnew);
            float p3 = __expf(s[i][3] - mnew);
            int r = ty * 4 + i;
            Ss[(tx*4+0)*68 + r] = p0;
            Ss[(tx*4+1)*68 + r] = p1;
            Ss[(tx*4+2)*68 + r] = p2;
            Ss[(tx*4+3)*68 + r] = p3;
            float sum = (p0 + p1) + (p2 + p3);
            sum += __shfl_xor_sync(0xffffffffu, sum, 1);
            sum += __shfl_xor_sync(0xffffffffu, sum, 2);
            sum += __shfl_xor_sync(0xffffffffu, sum, 4);
            sum += __shfl_xor_sync(0xffffffffu, sum, 8);
            li[i] = li[i] * corr + sum;
            mi[i] = mnew;
            ull cp = pk2(corr, corr);
            MUL2(acc2[i][0], cp);
            MUL2(acc2[i][1], cp);
        }
        __syncthreads();

        // acc += P.V : 4q x 4d per thread, FFMA2
        #pragma unroll 8
        for (int m = 0; m < 64; m++) {
            float4 pa = *(const float4*)&Ss[m * 68 + ty * 4];
            float4 vv = *(const float4*)&Vs[m * 68 + tx * 4];
            ull vp0 = pk2(vv.x, vv.y), vp1 = pk2(vv.z, vv.w);
            float pp[4] = {pa.x, pa.y, pa.z, pa.w};
            #pragma unroll
            for (int i = 0; i < 4; i++) {
                ull ap = pk2(pp[i], pp[i]);
                FMA2(acc2[i][0], ap, vp0);
                FMA2(acc2[i][1], ap, vp1);
            }
        }
    }

    // Writeout: att = acc / li, query-masked rows -> 0
    float* obase = att + ((size_t)b * NN + n0) * D + h * DS;
    #pragma unroll
    for (int i = 0; i < 4; i++) {
        int r = ty * 4 + i;
        float inv = 1.f / li[i];
        bool qm = xmb[n0 + r] != 0;
        float2 a0 = upk2(acc2[i][0]);
        float2 a1 = upk2(acc2[i][1]);
        float4 o;
        o.x = qm ? 0.f : a0.x * inv;
        o.y = qm ? 0.f : a0.y * inv;
        o.z = qm ? 0.f : a1.x * inv;
        o.w = qm ? 0.f : a1.y * inv;
        *(float4*)&obase[(size_t)r * D + tx * 4] = o;
    }
}

// ---------------------------------------------------------------------------
// out = LN(a' + b) * g + be
// mode bit0: zero OUTPUT rows where mask; bit1: zero `a` INPUT rows where mask
// ---------------------------------------------------------------------------
__global__ void __launch_bounds__(128) add_ln_k(
    const float* __restrict__ a, const float* __restrict__ bsrc,
    const float* __restrict__ g, const float* __restrict__ be,
    const int* __restrict__ xmask, int mode,
    float* __restrict__ out)
{
    int row = blockIdx.x;
    int t = threadIdx.x;
    const float* ar = a + (size_t)row * D;
    const float* br = bsrc + (size_t)row * D;
    bool rowmask = xmask[row] != 0;
    bool maska = (mode & 2) && rowmask;

    float vals[4];
    float s = 0.f;
    #pragma unroll
    for (int i = 0; i < 4; i++) {
        float av = maska ? 0.f : ar[t + i * 128];
        vals[i] = av + br[t + i * 128];
        s += vals[i];
    }
    __shared__ float red[4];
    #pragma unroll
    for (int o = 16; o; o >>= 1) s += __shfl_xor_sync(0xffffffffu, s, o);
    if ((t & 31) == 0) red[t >> 5] = s;
    __syncthreads();
    float mu = (red[0] + red[1] + red[2] + red[3]) * (1.f / 512.f);

    float s2 = 0.f;
    #pragma unroll
    for (int i = 0; i < 4; i++) { float d = vals[i] - mu; s2 += d * d; }
    __syncthreads();
    #pragma unroll
    for (int o = 16; o; o >>= 1) s2 += __shfl_xor_sync(0xffffffffu, s2, o);
    if ((t & 31) == 0) red[t >> 5] = s2;
    __syncthreads();
    float inv = rsqrtf((red[0] + red[1] + red[2] + red[3]) * (1.f / 512.f) + 1e-5f);

    bool maskout = (mode & 1) && rowmask;
    #pragma unroll
    for (int i = 0; i < 4; i++) {
        int c = t + i * 128;
        out[(size_t)row * D + c] = maskout ? 0.f : (vals[i] - mu) * inv * g[c] + be[c];
    }
}

// ---------------------------------------------------------------------------
extern "C" void kernel_launch(void* const* d_in, const int* in_sizes, int n_in,
                              void* d_out, int out_size)
{
    const float* x  = (const float*)d_in[0];
    const float* y  = (const float*)d_in[1];
    const int* xm = (const int*)d_in[2];
    const int* ym = (const int*)d_in[3];
    const float* Wq = (const float*)d_in[4];
    const float* Wk = (const float*)d_in[5];
    const float* Wv = (const float*)d_in[6];
    const float* Wo = (const float*)d_in[7];
    const float* W1 = (const float*)d_in[8];
    const float* b1 = (const float*)d_in[9];
    const float* W2 = (const float*)d_in[10];
    const float* b2 = (const float*)d_in[11];
    const float* g1 = (const float*)d_in[12];
    const float* be1= (const float*)d_in[13];
    const float* g2 = (const float*)d_in[14];
    const float* be2= (const float*)d_in[15];
    float* out = (float*)d_out;

    float *q, *k, *v, *att, *t1, *t2;
    cudaGetSymbolAddress((void**)&q,   S_q);
    cudaGetSymbolAddress((void**)&k,   S_k);
    cudaGetSymbolAddress((void**)&v,   S_v);
    cudaGetSymbolAddress((void**)&att, S_att);
    cudaGetSymbolAddress((void**)&t1,  S_t1);
    cudaGetSymbolAddress((void**)&t2,  S_t2);

    const int smem_attn = (4 * 64 * 68) * sizeof(float); // 69632
    cudaFuncSetAttribute(attn_k, cudaFuncAttributeMaxDynamicSharedMemorySize, smem_attn);

    dim3 gg(8, 64);   // 64-col tiles x 128-row tiles
    sgemm_k<4><<<gg, 256>>>(x, Wq, nullptr, xm, q);
    sgemm_k<4><<<gg, 256>>>(y, Wk, nullptr, ym, k);
    sgemm_k<4><<<gg, 256>>>(y, Wv, nullptr, ym, v);

    dim3 ga(16, 64);  // 16 q-tiles (64 each) x (B*H)
    attn_k<<<ga, 256, smem_attn>>>(q, k, v, xm, ym, att);

    sgemm_k<0><<<gg, 256>>>(att, Wo, nullptr, nullptr, t1);   // t1 = att@Wo
    add_ln_k<<<ROWS, 128>>>(x, t1, g1, be1, xm, 2, t2);        // t2 = LN1(x_masked + t1)
    sgemm_k<3><<<gg, 256>>>(t2, W1, b1, nullptr, q);           // q = relu(t2@W1+b1)
    sgemm_k<1><<<gg, 256>>>(q, W2, b2, nullptr, k);            // k = ff
    add_ln_k<<<ROWS, 128>>>(t2, k, g2, be2, xm, 1, out);       // out = LN2(t2+ff), masked
}

// round 7
// speedup vs baseline: 1.6216x; 1.6216x over previous
#include <cuda_runtime.h>
#include <math.h>

#define BB 8
#define NN 1024
#define MM 1024
#define D  512
#define HH 8
#define DS 64
#define ROWS (BB*NN)          // 8192
#define NEGV (-1e38f)
#define SCALE 0.04419417382415922f   // 1/sqrt(512)

typedef unsigned long long ull;

// packed f32x2 helpers (sm_100+)
__device__ __forceinline__ ull pk2(float lo, float hi) {
    ull r;
    asm("mov.b64 %0, {%1, %2};" : "=l"(r) : "f"(lo), "f"(hi));
    return r;
}
__device__ __forceinline__ float2 upk2(ull v) {
    float2 f;
    asm("mov.b64 {%0, %1}, %2;" : "=f"(f.x), "=f"(f.y) : "l"(v));
    return f;
}
#define FMA2(d, a, b) asm("fma.rn.f32x2 %0, %1, %2, %0;" : "+l"(d) : "l"(a), "l"(b))
#define MUL2(d, a)    asm("mul.rn.f32x2 %0, %0, %1;"    : "+l"(d) : "l"(a))

// Scratch (device globals; no allocation allowed)
__device__ float S_q  [ROWS*D];
__device__ float S_k  [ROWS*D];
__device__ float S_v  [ROWS*D];
__device__ float S_att[ROWS*D];
__device__ float S_t1 [ROWS*D];
__device__ float S_t2 [ROWS*D];

// ---------------------------------------------------------------------------
// SGEMM: C[ROWS,512] = A[ROWS,512] @ B[512,512]
// FLAGS: bit0 = +bias, bit1 = relu, bit2 = zero A rows where amask[row]!=0
// 128x64 tile, k-chunk 16, 256 threads, 4x8 microtile, FFMA2 inner,
// double-buffered smem, 3 CTAs/SM.
// ---------------------------------------------------------------------------
template<int FLAGS>
__global__ void __launch_bounds__(256, 3) sgemm_k(
    const float* __restrict__ A, const float* __restrict__ Bmat,
    const float* __restrict__ bias, const int* __restrict__ amask,
    float* __restrict__ C)
{
    __shared__ float As[2][16][132];   // [k][row] transposed
    __shared__ float Bs[2][16][68];    // [k][col]
    const int t  = threadIdx.x;
    const int tx = t & 7, ty = t >> 3;            // tx: 8 col-groups, ty: 32 row-groups
    const int row0 = blockIdx.y * 128, col0 = blockIdx.x * 64;
    const int ar = t >> 1, ak = (t & 1) * 8;      // A: 2 threads/row, 8 k each
    const int bk = t >> 4, bn = (t & 15) * 4;     // B: 16 k-rows, 16 threads/row

    const bool am = (FLAGS & 4) && (amask[row0 + ar] != 0);
    const float* Aptr = A + (size_t)(row0 + ar) * D + ak;
    const float* Bptr = Bmat + (size_t)bk * D + col0 + bn;

    float4 av0 = *(const float4*)Aptr;
    float4 av1 = *(const float4*)(Aptr + 4);
    float4 bv  = *(const float4*)Bptr;
    if (am) { av0 = make_float4(0,0,0,0); av1 = make_float4(0,0,0,0); }
    As[0][ak+0][ar] = av0.x; As[0][ak+1][ar] = av0.y;
    As[0][ak+2][ar] = av0.z; As[0][ak+3][ar] = av0.w;
    As[0][ak+4][ar] = av1.x; As[0][ak+5][ar] = av1.y;
    As[0][ak+6][ar] = av1.z; As[0][ak+7][ar] = av1.w;
    *(float4*)&Bs[0][bk][bn] = bv;
    __syncthreads();

    ull acc2[4][4] = {};   // 4 rows x (2 cols-pairs per 32-block x 2 blocks)

    #pragma unroll 1
    for (int c = 0; c < 32; c++) {
        int cur = c & 1;
        if (c < 31) {
            av0 = *(const float4*)(Aptr + (c + 1) * 16);
            av1 = *(const float4*)(Aptr + (c + 1) * 16 + 4);
            bv  = *(const float4*)(Bptr + (size_t)(c + 1) * 16 * D);
            if (am) { av0 = make_float4(0,0,0,0); av1 = make_float4(0,0,0,0); }
        }
        #pragma unroll
        for (int kk = 0; kk < 16; kk++) {
            float4 a  = *(const float4*)&As[cur][kk][ty * 4];
            float4 b0 = *(const float4*)&Bs[cur][kk][tx * 4];
            float4 b1 = *(const float4*)&Bs[cur][kk][32 + tx * 4];
            ull bp0 = pk2(b0.x, b0.y), bp1 = pk2(b0.z, b0.w);
            ull bp2 = pk2(b1.x, b1.y), bp3 = pk2(b1.z, b1.w);
            float ra[4] = {a.x, a.y, a.z, a.w};
            #pragma unroll
            for (int i = 0; i < 4; i++) {
                ull ap = pk2(ra[i], ra[i]);
                FMA2(acc2[i][0], ap, bp0);
                FMA2(acc2[i][1], ap, bp1);
                FMA2(acc2[i][2], ap, bp2);
                FMA2(acc2[i][3], ap, bp3);
            }
        }
        if (c < 31) {
            int nxt = cur ^ 1;
            As[nxt][ak+0][ar] = av0.x; As[nxt][ak+1][ar] = av0.y;
            As[nxt][ak+2][ar] = av0.z; As[nxt][ak+3][ar] = av0.w;
            As[nxt][ak+4][ar] = av1.x; As[nxt][ak+5][ar] = av1.y;
            As[nxt][ak+6][ar] = av1.z; As[nxt][ak+7][ar] = av1.w;
            *(float4*)&Bs[nxt][bk][bn] = bv;
            __syncthreads();
        }
    }

    #pragma unroll
    for (int i = 0; i < 4; i++) {
        int row = row0 + ty * 4 + i;
        #pragma unroll
        for (int cb = 0; cb < 2; cb++) {
            int col = col0 + cb * 32 + tx * 4;
            float2 v0 = upk2(acc2[i][cb * 2 + 0]);
            float2 v1 = upk2(acc2[i][cb * 2 + 1]);
            float vv[4] = {v0.x, v0.y, v1.x, v1.y};
            #pragma unroll
            for (int j = 0; j < 4; j++) {
                if (FLAGS & 1) vv[j] += bias[col + j];
                if (FLAGS & 2) vv[j] = fmaxf(vv[j], 0.f);
            }
            *(float4*)&C[(size_t)row * D + col] =
                make_float4(vv[0], vv[1], vv[2], vv[3]);
        }
    }
}

// ---------------------------------------------------------------------------
// Flash attention: one CTA = (b,h, 64-query tile). Online softmax over M=1024.
// 16x16 threads, 4q x 4k per thread, FFMA2, register softmax, 3 CTAs/SM.
// ---------------------------------------------------------------------------
__global__ void __launch_bounds__(256, 3) attn_k(
    const float* __restrict__ q, const float* __restrict__ k,
    const float* __restrict__ v,
    const int* __restrict__ xmask,
    const int* __restrict__ ymask,
    float* __restrict__ att)
{
    extern __shared__ float sm[];
    float* Qs = sm;              // [d=64][q=68]  pre-scaled
    float* Ks = Qs + 64 * 68;    // [d=64][k=68]
    float* Vs = Ks + 64 * 68;    // [m=64][d=68]
    float* Ss = Vs + 64 * 68;    // [k=64][q=68]  (exp'd P)

    const int bh = blockIdx.y;
    const int b  = bh >> 3, h = bh & 7;
    const int n0 = blockIdx.x * 64;
    const int t  = threadIdx.x;
    const int tx = t & 15, ty = t >> 4;

    const float* qbase = q + ((size_t)b * NN + n0) * D + h * DS;
    const float* kbase = k + (size_t)b * MM * D + h * DS;
    const float* vbase = v + (size_t)b * MM * D + h * DS;
    const int* ymb = ymask + b * MM;
    const int* xmb = xmask + b * NN;

    // Load Q tile (64x64) transposed into [d][q], scaled
    {
        int r = t >> 2;
        #pragma unroll
        for (int dd = 0; dd < 4; dd++) {
            int d4 = (t & 3) * 4 + dd * 16;
            float4 qa = *(const float4*)&qbase[(size_t)r * D + d4];
            Qs[(d4+0)*68 + r] = qa.x * SCALE; Qs[(d4+1)*68 + r] = qa.y * SCALE;
            Qs[(d4+2)*68 + r] = qa.z * SCALE; Qs[(d4+3)*68 + r] = qa.w * SCALE;
        }
    }

    float mi[4] = {-3.0e38f, -3.0e38f, -3.0e38f, -3.0e38f};
    float li[4] = {0.f, 0.f, 0.f, 0.f};
    ull acc2[4][2] = {};

    for (int m0 = 0; m0 < MM; m0 += 64) {
        __syncthreads();
        {
            int r = t >> 2;
            #pragma unroll
            for (int dd = 0; dd < 4; dd++) {
                int d4 = (t & 3) * 4 + dd * 16;
                float4 kv = *(const float4*)&kbase[(size_t)(m0 + r) * D + d4];
                Ks[(d4+0)*68 + r] = kv.x; Ks[(d4+1)*68 + r] = kv.y;
                Ks[(d4+2)*68 + r] = kv.z; Ks[(d4+3)*68 + r] = kv.w;
                float4 vv = *(const float4*)&vbase[(size_t)(m0 + r) * D + d4];
                *(float4*)&Vs[r * 68 + d4] = vv;
            }
        }
        __syncthreads();

        // S = (Q*SCALE).K^T : 4q x 4k per thread, FFMA2
        ull s2[4][2] = {};
        #pragma unroll 8
        for (int d = 0; d < 64; d++) {
            float4 qa = *(const float4*)&Qs[d * 68 + ty * 4];
            float4 kq = *(const float4*)&Ks[d * 68 + tx * 4];
            ull kp0 = pk2(kq.x, kq.y), kp1 = pk2(kq.z, kq.w);
            float qq[4] = {qa.x, qa.y, qa.z, qa.w};
            #pragma unroll
            for (int i = 0; i < 4; i++) {
                ull ap = pk2(qq[i], qq[i]);
                FMA2(s2[i][0], ap, kp0);
                FMA2(s2[i][1], ap, kp1);
            }
        }

        // unpack + key-mask
        float s[4][4];
        int km0 = ymb[m0 + tx * 4 + 0], km1 = ymb[m0 + tx * 4 + 1];
        int km2 = ymb[m0 + tx * 4 + 2], km3 = ymb[m0 + tx * 4 + 3];
        #pragma unroll
        for (int i = 0; i < 4; i++) {
            float2 v0 = upk2(s2[i][0]);
            float2 v1 = upk2(s2[i][1]);
            s[i][0] = km0 ? NEGV : v0.x;
            s[i][1] = km1 ? NEGV : v0.y;
            s[i][2] = km2 ? NEGV : v1.x;
            s[i][3] = km3 ? NEGV : v1.y;
        }

        // online softmax in registers (reduce across 16 tx lanes)
        #pragma unroll
        for (int i = 0; i < 4; i++) {
            float mx = fmaxf(fmaxf(s[i][0], s[i][1]), fmaxf(s[i][2], s[i][3]));
            mx = fmaxf(mx, __shfl_xor_sync(0xffffffffu, mx, 1));
            mx = fmaxf(mx, __shfl_xor_sync(0xffffffffu, mx, 2));
            mx = fmaxf(mx, __shfl_xor_sync(0xffffffffu, mx, 4));
            mx = fmaxf(mx, __shfl_xor_sync(0xffffffffu, mx, 8));
            float mnew = fmaxf(mi[i], mx);
            float corr = __expf(mi[i] - mnew);
            float p0 = __expf(s[i][0] - mnew);
            float p1 = __expf(s[i][1] - mnew);
            float p2 = __expf(s[i][2] - mnew);
            float p3 = __expf(s[i][3] - mnew);
            int r = ty * 4 + i;
            Ss[(tx*4+0)*68 + r] = p0;
            Ss[(tx*4+1)*68 + r] = p1;
            Ss[(tx*4+2)*68 + r] = p2;
            Ss[(tx*4+3)*68 + r] = p3;
            float sum = (p0 + p1) + (p2 + p3);
            sum += __shfl_xor_sync(0xffffffffu, sum, 1);
            sum += __shfl_xor_sync(0xffffffffu, sum, 2);
            sum += __shfl_xor_sync(0xffffffffu, sum, 4);
            sum += __shfl_xor_sync(0xffffffffu, sum, 8);
            li[i] = li[i] * corr + sum;
            mi[i] = mnew;
            ull cp = pk2(corr, corr);
            MUL2(acc2[i][0], cp);
            MUL2(acc2[i][1], cp);
        }
        __syncthreads();

        // acc += P.V : 4q x 4d per thread, FFMA2
        #pragma unroll 8
        for (int m = 0; m < 64; m++) {
            float4 pa = *(const float4*)&Ss[m * 68 + ty * 4];
            float4 vv = *(const float4*)&Vs[m * 68 + tx * 4];
            ull vp0 = pk2(vv.x, vv.y), vp1 = pk2(vv.z, vv.w);
            float pp[4] = {pa.x, pa.y, pa.z, pa.w};
            #pragma unroll
            for (int i = 0; i < 4; i++) {
                ull ap = pk2(pp[i], pp[i]);
                FMA2(acc2[i][0], ap, vp0);
                FMA2(acc2[i][1], ap, vp1);
            }
        }
    }

    // Writeout: att = acc / li, query-masked rows -> 0
    float* obase = att + ((size_t)b * NN + n0) * D + h * DS;
    #pragma unroll
    for (int i = 0; i < 4; i++) {
        int r = ty * 4 + i;
        float inv = 1.f / li[i];
        bool qm = xmb[n0 + r] != 0;
        float2 a0 = upk2(acc2[i][0]);
        float2 a1 = upk2(acc2[i][1]);
        float4 o;
        o.x = qm ? 0.f : a0.x * inv;
        o.y = qm ? 0.f : a0.y * inv;
        o.z = qm ? 0.f : a1.x * inv;
        o.w = qm ? 0.f : a1.y * inv;
        *(float4*)&obase[(size_t)r * D + tx * 4] = o;
    }
}

// ---------------------------------------------------------------------------
// out = LN(a' + b) * g + be
// mode bit0: zero OUTPUT rows where mask; bit1: zero `a` INPUT rows where mask
// ---------------------------------------------------------------------------
__global__ void __launch_bounds__(128) add_ln_k(
    const float* __restrict__ a, const float* __restrict__ bsrc,
    const float* __restrict__ g, const float* __restrict__ be,
    const int* __restrict__ xmask, int mode,
    float* __restrict__ out)
{
    int row = blockIdx.x;
    int t = threadIdx.x;
    const float* ar = a + (size_t)row * D;
    const float* br = bsrc + (size_t)row * D;
    bool rowmask = xmask[row] != 0;
    bool maska = (mode & 2) && rowmask;

    float vals[4];
    float s = 0.f;
    #pragma unroll
    for (int i = 0; i < 4; i++) {
        float av = maska ? 0.f : ar[t + i * 128];
        vals[i] = av + br[t + i * 128];
        s += vals[i];
    }
    __shared__ float red[4];
    #pragma unroll
    for (int o = 16; o; o >>= 1) s += __shfl_xor_sync(0xffffffffu, s, o);
    if ((t & 31) == 0) red[t >> 5] = s;
    __syncthreads();
    float mu = (red[0] + red[1] + red[2] + red[3]) * (1.f / 512.f);

    float s2 = 0.f;
    #pragma unroll
    for (int i = 0; i < 4; i++) { float d = vals[i] - mu; s2 += d * d; }
    __syncthreads();
    #pragma unroll
    for (int o = 16; o; o >>= 1) s2 += __shfl_xor_sync(0xffffffffu, s2, o);
    if ((t & 31) == 0) red[t >> 5] = s2;
    __syncthreads();
    float inv = rsqrtf((red[0] + red[1] + red[2] + red[3]) * (1.f / 512.f) + 1e-5f);

    bool maskout = (mode & 1) && rowmask;
    #pragma unroll
    for (int i = 0; i < 4; i++) {
        int c = t + i * 128;
        out[(size_t)row * D + c] = maskout ? 0.f : (vals[i] - mu) * inv * g[c] + be[c];
    }
}

// ---------------------------------------------------------------------------
extern "C" void kernel_launch(void* const* d_in, const int* in_sizes, int n_in,
                              void* d_out, int out_size)
{
    const float* x  = (const float*)d_in[0];
    const float* y  = (const float*)d_in[1];
    const int* xm = (const int*)d_in[2];
    const int* ym = (const int*)d_in[3];
    const float* Wq = (const float*)d_in[4];
    const float* Wk = (const float*)d_in[5];
    const float* Wv = (const float*)d_in[6];
    const float* Wo = (const float*)d_in[7];
    const float* W1 = (const float*)d_in[8];
    const float* b1 = (const float*)d_in[9];
    const float* W2 = (const float*)d_in[10];
    const float* b2 = (const float*)d_in[11];
    const float* g1 = (const float*)d_in[12];
    const float* be1= (const float*)d_in[13];
    const float* g2 = (const float*)d_in[14];
    const float* be2= (const float*)d_in[15];
    float* out = (float*)d_out;

    float *q, *k, *v, *att, *t1, *t2;
    cudaGetSymbolAddress((void**)&q,   S_q);
    cudaGetSymbolAddress((void**)&k,   S_k);
    cudaGetSymbolAddress((void**)&v,   S_v);
    cudaGetSymbolAddress((void**)&att, S_att);
    cudaGetSymbolAddress((void**)&t1,  S_t1);
    cudaGetSymbolAddress((void**)&t2,  S_t2);

    const int smem_attn = (4 * 64 * 68) * sizeof(float); // 69632
    cudaFuncSetAttribute(attn_k, cudaFuncAttributeMaxDynamicSharedMemorySize, smem_attn);

    dim3 gg(8, 64);   // 64-col tiles x 128-row tiles
    sgemm_k<4><<<gg, 256>>>(x, Wq, nullptr, xm, q);
    sgemm_k<4><<<gg, 256>>>(y, Wk, nullptr, ym, k);
    sgemm_k<4><<<gg, 256>>>(y, Wv, nullptr, ym, v);

    dim3 ga(16, 64);  // 16 q-tiles (64 each) x (B*H)
    attn_k<<<ga, 256, smem_attn>>>(q, k, v, xm, ym, att);

    sgemm_k<0><<<gg, 256>>>(att, Wo, nullptr, nullptr, t1);   // t1 = att@Wo
    add_ln_k<<<ROWS, 128>>>(x, t1, g1, be1, xm, 2, t2);        // t2 = LN1(x_masked + t1)
    sgemm_k<3><<<gg, 256>>>(t2, W1, b1, nullptr, q);           // q = relu(t2@W1+b1)
    sgemm_k<1><<<gg, 256>>>(q, W2, b2, nullptr, k);            // k = ff
    add_ln_k<<<ROWS, 128>>>(t2, k, g2, be2, xm, 1, out);       // out = LN2(t2+ff), masked
}